// round 11
// baseline (speedup 1.0000x reference)
#include <cuda_runtime.h>

// VectorNormSelection, round 11: value-only IMNMX network + rank-scatter.
// Fast path (all-distinct norms, ~always):
//   - R10-validated bitonic wiring on u32 norm BITS only (nonneg floats:
//     unsigned order == float order). Each compare-exchange is ONE
//     predicate-selected IMNMX (takeMax ? max : min), vs ~4 ALU ops for the
//     (value,index) pair network. Sorted top-16 values land in lanes 0-7.
//   - each lane binary-searches its 2 own norms in the sorted 16 (4 steps,
//     shfl-fetched probes) -> exact rank; rank<16 scatters the lane's
//     already-loaded 3-vector to out[row][rank][:]. No gather loads.
// Tie safety (exactness): if any duplicate value affects the top-16
//   (adjacent-equal in sorted 16, or >=2 elements with rank 15), the warp
//   reruns the row with the R7 exact u64 (value<<32 | 63-idx) network +
//   gather epilogue -- bit-exact jax.lax.top_k semantics either way.

#define WPB 8          // warps per block
#define RPW 4          // rows per warp
#define FULLM 0xffffffffu

typedef unsigned u32;
typedef unsigned long long u64;

// ---------- value-only stages (1 IMNMX per element) ----------
template <int JH>
__device__ __forceinline__ void vstage_x(u32& e0, u32& e1, bool takeMax) {
    u32 p0 = __shfl_xor_sync(FULLM, e0, JH);
    u32 p1 = __shfl_xor_sync(FULLM, e1, JH);
    e0 = takeMax ? max(e0, p0) : min(e0, p0);
    e1 = takeMax ? max(e1, p1) : min(e1, p1);
}
__device__ __forceinline__ void vstage_l(u32& e0, u32& e1, bool descR) {
    u32 a = e0, b = e1;
    e0 = descR ? max(a, b) : min(a, b);
    e1 = descR ? min(a, b) : max(a, b);
}
template <int XM>
__device__ __forceinline__ void vhalve_x(u32& e0, u32& e1) {
    u32 p0 = __shfl_xor_sync(FULLM, e0, XM);
    u32 p1 = __shfl_xor_sync(FULLM, e1, XM);
    e0 = max(e0, p1);
    e1 = max(e1, p0);
}

// ---------- exact u64 stages (slow path; R7-validated) ----------
__device__ __forceinline__ u64 cexg(u64 e, u64 p, bool takeMax) {
    return ((p > e) == takeMax) ? p : e;
}
template <int JH>
__device__ __forceinline__ void kstage_x(u64& e0, u64& e1, bool takeMax) {
    u64 p0 = __shfl_xor_sync(FULLM, e0, JH);
    u64 p1 = __shfl_xor_sync(FULLM, e1, JH);
    e0 = cexg(e0, p0, takeMax);
    e1 = cexg(e1, p1, takeMax);
}
__device__ __forceinline__ void kstage_l(u64& e0, u64& e1, bool descR) {
    bool gt = e0 > e1;
    u64 hi = gt ? e0 : e1;
    u64 lo = gt ? e1 : e0;
    e0 = descR ? hi : lo;
    e1 = descR ? lo : hi;
}
template <int XM>
__device__ __forceinline__ void khalve_x(u64& e0, u64& e1) {
    u64 p0 = __shfl_xor_sync(FULLM, e0, XM);
    u64 p1 = __shfl_xor_sync(FULLM, e1, XM);
    e0 = (p1 > e0) ? p1 : e0;
    e1 = (p0 > e1) ? p0 : e1;
}

// fetch sorted value at position pos (0..15) from lanes 0-7 (2/lane)
__device__ __forceinline__ u32 fetch16(u32 e0, u32 e1, int pos) {
    u32 a = __shfl_sync(FULLM, e0, pos >> 1);
    u32 b = __shfl_sync(FULLM, e1, pos >> 1);
    return (pos & 1) ? b : a;
}

__global__ void __launch_bounds__(WPB * 32)
vecnorm_topk_kernel(const float* __restrict__ x, float* __restrict__ out, int nrows)
{
    const int lane = threadIdx.x & 31;
    const int wg   = blockIdx.x * WPB + (threadIdx.x >> 5);
    const int rowBase = wg * RPW;
    if (rowBase >= nrows) return;
    const int rowsHere = min(RPW, nrows - rowBase);

    // hoisted direction predicates (row-independent; identical to R10)
    const bool d2 = ((lane & 1) == 0);
    const bool d4 = ((lane & 2) == 0);
    const bool d8 = ((lane & 4) == 0);
    const bool x1_d4 = (d2 == d4);
    const bool x2_d8 = (((lane & 2) == 0) == d8);
    const bool x1_d8 = (d2 == d8);
    const bool x4_T  = ((lane & 4) == 0);
    const bool x2_T  = ((lane & 2) == 0);
    const bool x1_T  = d2;

    // slow-path gather routing constants
    const int f2 = 32 + lane;
    const int j1 = lane / 3, c1 = lane - 3 * j1;
    const int j2 = f2 / 3,   c2 = f2 - 3 * j2;

    const float* xr   = x   + (size_t)rowBase * 192;
    float*       outr = out + (size_t)rowBase * 48;

#pragma unroll 1
    for (int i = 0; i < rowsHere; i++) {
        // ---- load 6 floats (vectors 2*lane, 2*lane+1), coalesced ----
        const float2* xr2 = reinterpret_cast<const float2*>(xr);
        float2 a = xr2[3 * lane + 0];
        float2 b = xr2[3 * lane + 1];
        float2 c = xr2[3 * lane + 2];
        float n0 = fmaf(a.x, a.x, fmaf(a.y, a.y, b.x * b.x));
        float n1 = fmaf(b.y, b.y, fmaf(c.x, c.x, c.y * c.y));
        u32 w0 = __float_as_uint(n0);      // nonneg: bit order == float order
        u32 w1 = __float_as_uint(n1);

        // ---- value-only bitonic: sort-16 per 8-lane group, 2 tree merges ----
        u32 e0 = w0, e1 = w1;
        vstage_l(e0, e1, d2);              // k=2  j=1
        vstage_x<1>(e0, e1, x1_d4);        // k=4  j=2
        vstage_l(e0, e1, d4);              //      j=1
        vstage_x<2>(e0, e1, x2_d8);        // k=8  j=4
        vstage_x<1>(e0, e1, x1_d8);        //      j=2
        vstage_l(e0, e1, d8);              //      j=1
        vstage_x<4>(e0, e1, x4_T);         // k=16 j=8
        vstage_x<2>(e0, e1, x2_T);         //      j=4
        vstage_x<1>(e0, e1, x1_T);         //      j=2
        vstage_l(e0, e1, true);            //      j=1

        vhalve_x<15>(e0, e1);              // merge A
        vstage_x<4>(e0, e1, x4_T);
        vstage_x<2>(e0, e1, x2_T);
        vstage_x<1>(e0, e1, x1_T);
        vstage_l(e0, e1, true);

        vhalve_x<23>(e0, e1);              // merge B -> top-16 in lanes 0-7
        vstage_x<4>(e0, e1, x4_T);
        vstage_x<2>(e0, e1, x2_T);
        vstage_x<1>(e0, e1, x1_T);
        vstage_l(e0, e1, true);

        // ---- rank own elements: r = #(sorted > w), 4-step binary search ----
        int r0 = 0, r1 = 0;
#pragma unroll
        for (int s = 8; s >= 1; s >>= 1) {
            u32 v0 = fetch16(e0, e1, r0 + s - 1);
            if (v0 > w0) r0 += s;
            u32 v1 = fetch16(e0, e1, r1 + s - 1);
            if (v1 > w1) r1 += s;
        }

        // ---- tie detection (warp-uniform) ----
        u32 nxt = __shfl_sync(FULLM, e0, (lane + 1) & 31);
        bool adj = (lane < 8 && e0 == e1) || (lane < 7 && e1 == nxt);
        int c15 = __popc(__ballot_sync(FULLM, r0 == 15)) +
                  __popc(__ballot_sync(FULLM, r1 == 15));
        bool anyTie = __any_sync(FULLM, adj) || (c15 >= 2);

        if (!anyTie) {
            // ---- scatter own vectors by rank (no gather loads) ----
            if (r0 < 16) {
                float* p = outr + 3 * r0;
                p[0] = a.x; p[1] = a.y; p[2] = b.x;
            }
            if (r1 < 16) {
                float* p = outr + 3 * r1;
                p[0] = b.y; p[1] = c.x; p[2] = c.y;
            }
        } else {
            // ---- exact u64 network (R7-validated) + gather epilogue ----
            u64 k0 = ((u64)w0 << 32) | (u64)(63 - 2 * lane);
            u64 k1 = ((u64)w1 << 32) | (u64)(62 - 2 * lane);
            kstage_l(k0, k1, d2);
            kstage_x<1>(k0, k1, x1_d4);
            kstage_l(k0, k1, d4);
            kstage_x<2>(k0, k1, x2_d8);
            kstage_x<1>(k0, k1, x1_d8);
            kstage_l(k0, k1, d8);
            kstage_x<4>(k0, k1, x4_T);
            kstage_x<2>(k0, k1, x2_T);
            kstage_x<1>(k0, k1, x1_T);
            kstage_l(k0, k1, true);
            khalve_x<15>(k0, k1);
            kstage_x<4>(k0, k1, x4_T);
            kstage_x<2>(k0, k1, x2_T);
            kstage_x<1>(k0, k1, x1_T);
            kstage_l(k0, k1, true);
            khalve_x<23>(k0, k1);
            kstage_x<4>(k0, k1, x4_T);
            kstage_x<2>(k0, k1, x2_T);
            kstage_x<1>(k0, k1, x1_T);
            kstage_l(k0, k1, true);

            unsigned idx0 = 63u - (unsigned)(k0 & 63ull);
            unsigned idx1 = 63u - (unsigned)(k1 & 63ull);
            unsigned pk = idx0 | (idx1 << 8);
            unsigned pkA = __shfl_sync(FULLM, pk, j1 >> 1);
            unsigned iA  = (j1 & 1) ? ((pkA >> 8) & 0xffu) : (pkA & 0xffu);
            unsigned pkB = __shfl_sync(FULLM, pk, j2 >> 1);
            unsigned iB  = (j2 & 1) ? ((pkB >> 8) & 0xffu) : (pkB & 0xffu);
            outr[lane] = xr[(int)iA * 3 + c1];
            if (lane < 16)
                outr[32 + lane] = xr[(int)iB * 3 + c2];
        }

        xr   += 192;
        outr += 48;
    }
}

extern "C" void kernel_launch(void* const* d_in, const int* in_sizes, int n_in,
                              void* d_out, int out_size)
{
    const float* x   = (const float*)d_in[0];
    float*       out = (float*)d_out;
    int nrows = in_sizes[0] / 192;
    int rowsPerBlock = WPB * RPW;
    int grid = (nrows + rowsPerBlock - 1) / rowsPerBlock;
    vecnorm_topk_kernel<<<grid, WPB * 32>>>(x, out, nrows);
}

// round 12
// speedup vs baseline: 2.4593x; 2.4593x over previous
#include <cuda_runtime.h>

// VectorNormSelection, round 12: packed u32 keys + exactness detector.
// Fast path: R7-wired bitonic network on SINGLE u32 keys
//     k = (norm_bits & ~63) | (63 - idx)
//   (1 compare+select per cex, half the SHFL traffic of the u64 network).
//   Truncating 6 value bits can only misorder pairs whose values agree in the
//   top 26 bits. The result is provably bit-exact top_k iff (a) the 16 sorted
//   keys have pairwise-distinct high-26 fields, and (b) no other element
//   shares rank-15's high-26 field. Both conditions are checked warp-wide in
//   ~12 ops; violation (~0.5% of rows) takes the slow path:
// Slow path: R7's validated exact u64 (norm_bits<<32 | 63-idx) network.
// Both paths end in the same gather epilogue -> exact jax.lax.top_k always.

#define WPB 8          // warps per block
#define RPW 4          // rows per warp
#define FULLM 0xffffffffu

typedef unsigned u32;
typedef unsigned long long u64;

// ---------- packed u32 stages ----------
template <int JH>
__device__ __forceinline__ void pstage_x(u32& e0, u32& e1, bool takeMax) {
    u32 p0 = __shfl_xor_sync(FULLM, e0, JH);
    u32 p1 = __shfl_xor_sync(FULLM, e1, JH);
    e0 = takeMax ? max(e0, p0) : min(e0, p0);
    e1 = takeMax ? max(e1, p1) : min(e1, p1);
}
__device__ __forceinline__ void pstage_l(u32& e0, u32& e1, bool descR) {
    u32 hi = max(e0, e1), lo = min(e0, e1);
    e0 = descR ? hi : lo;
    e1 = descR ? lo : hi;
}
template <int XM>
__device__ __forceinline__ void phalve_x(u32& e0, u32& e1) {
    u32 p0 = __shfl_xor_sync(FULLM, e0, XM);
    u32 p1 = __shfl_xor_sync(FULLM, e1, XM);
    e0 = max(e0, p1);
    e1 = max(e1, p0);
}

// ---------- exact u64 stages (slow path; R7-validated) ----------
__device__ __forceinline__ u64 cexg(u64 e, u64 p, bool takeMax) {
    return ((p > e) == takeMax) ? p : e;
}
template <int JH>
__device__ __forceinline__ void kstage_x(u64& e0, u64& e1, bool takeMax) {
    u64 p0 = __shfl_xor_sync(FULLM, e0, JH);
    u64 p1 = __shfl_xor_sync(FULLM, e1, JH);
    e0 = cexg(e0, p0, takeMax);
    e1 = cexg(e1, p1, takeMax);
}
__device__ __forceinline__ void kstage_l(u64& e0, u64& e1, bool descR) {
    bool gt = e0 > e1;
    u64 hi = gt ? e0 : e1;
    u64 lo = gt ? e1 : e0;
    e0 = descR ? hi : lo;
    e1 = descR ? lo : hi;
}
template <int XM>
__device__ __forceinline__ void khalve_x(u64& e0, u64& e1) {
    u64 p0 = __shfl_xor_sync(FULLM, e0, XM);
    u64 p1 = __shfl_xor_sync(FULLM, e1, XM);
    e0 = (p1 > e0) ? p1 : e0;
    e1 = (p0 > e1) ? p0 : e1;
}

__global__ void __launch_bounds__(WPB * 32)
vecnorm_topk_kernel(const float* __restrict__ x, float* __restrict__ out, int nrows)
{
    const int lane = threadIdx.x & 31;
    const int wg   = blockIdx.x * WPB + (threadIdx.x >> 5);
    const int rowBase = wg * RPW;
    if (rowBase >= nrows) return;
    const int rowsHere = min(RPW, nrows - rowBase);

    // hoisted direction predicates (row-independent; R10-validated wiring)
    const bool d2 = ((lane & 1) == 0);
    const bool d4 = ((lane & 2) == 0);
    const bool d8 = ((lane & 4) == 0);
    const bool x1_d4 = (d2 == d4);
    const bool x2_d8 = (((lane & 2) == 0) == d8);
    const bool x1_d8 = (d2 == d8);
    const bool x4_T  = ((lane & 4) == 0);
    const bool x2_T  = ((lane & 2) == 0);
    const bool x1_T  = d2;

    // gather routing constants
    const int f2 = 32 + lane;
    const int j1 = lane / 3, c1 = lane - 3 * j1;
    const int j2 = f2 / 3,   c2 = f2 - 3 * j2;

    const u32 tag0 = (u32)(63 - 2 * lane);   // 63 - idx for element 0
    const u32 tag1 = (u32)(62 - 2 * lane);   // 63 - idx for element 1

    const float* xr   = x   + (size_t)rowBase * 192;
    float*       outr = out + (size_t)rowBase * 48;

#pragma unroll 1
    for (int i = 0; i < rowsHere; i++) {
        // ---- load 6 floats (vectors 2*lane, 2*lane+1), coalesced ----
        const float2* xr2 = reinterpret_cast<const float2*>(xr);
        float2 a = xr2[3 * lane + 0];
        float2 b = xr2[3 * lane + 1];
        float2 c = xr2[3 * lane + 2];
        float n0 = fmaf(a.x, a.x, fmaf(a.y, a.y, b.x * b.x));
        float n1 = fmaf(b.y, b.y, fmaf(c.x, c.x, c.y * c.y));
        u32 w0 = __float_as_uint(n0);        // nonneg: bit order == float order
        u32 w1 = __float_as_uint(n1);

        // ---- fast path: packed-key bitonic network ----
        u32 k0 = (w0 & 0xFFFFFFC0u) | tag0;
        u32 k1 = (w1 & 0xFFFFFFC0u) | tag1;

        pstage_l(k0, k1, d2);                // k=2  j=1
        pstage_x<1>(k0, k1, x1_d4);          // k=4  j=2
        pstage_l(k0, k1, d4);                //      j=1
        pstage_x<2>(k0, k1, x2_d8);          // k=8  j=4
        pstage_x<1>(k0, k1, x1_d8);          //      j=2
        pstage_l(k0, k1, d8);                //      j=1
        pstage_x<4>(k0, k1, x4_T);           // k=16 j=8
        pstage_x<2>(k0, k1, x2_T);           //      j=4
        pstage_x<1>(k0, k1, x1_T);           //      j=2
        pstage_l(k0, k1, true);              //      j=1

        phalve_x<15>(k0, k1);                // merge A
        pstage_x<4>(k0, k1, x4_T);
        pstage_x<2>(k0, k1, x2_T);
        pstage_x<1>(k0, k1, x1_T);
        pstage_l(k0, k1, true);

        phalve_x<23>(k0, k1);                // merge B -> top-16 in lanes 0-7
        pstage_x<4>(k0, k1, x4_T);
        pstage_x<2>(k0, k1, x2_T);
        pstage_x<1>(k0, k1, x1_T);
        pstage_l(k0, k1, true);

        // ---- exactness detector (warp-uniform) ----
        u32 v0t = k0 >> 6, v1t = k1 >> 6;               // high-26 value fields
        u32 nv0 = __shfl_down_sync(FULLM, v0t, 1);      // next lane's rank(2L+2)
        bool adj = (lane < 8 && v0t == v1t) || (lane < 7 && v1t == nv0);
        u32 t26 = __shfl_sync(FULLM, v1t, 7);           // rank-15 high-26
        int tot = __popc(__ballot_sync(FULLM, (w0 >> 6) == t26)) +
                  __popc(__ballot_sync(FULLM, (w1 >> 6) == t26));
        bool slow = __any_sync(FULLM, adj) || (tot >= 2);

        unsigned idx0, idx1;
        if (!slow) {
            idx0 = 63u - (k0 & 63u);
            idx1 = 63u - (k1 & 63u);
        } else {
            // ---- slow path: exact u64 network (R7-validated) ----
            u64 e0 = ((u64)w0 << 32) | (u64)tag0;
            u64 e1 = ((u64)w1 << 32) | (u64)tag1;
            kstage_l(e0, e1, d2);
            kstage_x<1>(e0, e1, x1_d4);
            kstage_l(e0, e1, d4);
            kstage_x<2>(e0, e1, x2_d8);
            kstage_x<1>(e0, e1, x1_d8);
            kstage_l(e0, e1, d8);
            kstage_x<4>(e0, e1, x4_T);
            kstage_x<2>(e0, e1, x2_T);
            kstage_x<1>(e0, e1, x1_T);
            kstage_l(e0, e1, true);
            khalve_x<15>(e0, e1);
            kstage_x<4>(e0, e1, x4_T);
            kstage_x<2>(e0, e1, x2_T);
            kstage_x<1>(e0, e1, x1_T);
            kstage_l(e0, e1, true);
            khalve_x<23>(e0, e1);
            kstage_x<4>(e0, e1, x4_T);
            kstage_x<2>(e0, e1, x2_T);
            kstage_x<1>(e0, e1, x1_T);
            kstage_l(e0, e1, true);
            idx0 = 63u - (unsigned)(e0 & 63ull);
            idx1 = 63u - (unsigned)(e1 & 63ull);
        }

        // ---- shared epilogue: broadcast indices, gather (L1-hot), store ----
        unsigned pk = idx0 | (idx1 << 8);
        unsigned pkA = __shfl_sync(FULLM, pk, j1 >> 1);
        unsigned iA  = (j1 & 1) ? ((pkA >> 8) & 0xffu) : (pkA & 0xffu);
        unsigned pkB = __shfl_sync(FULLM, pk, j2 >> 1);
        unsigned iB  = (j2 & 1) ? ((pkB >> 8) & 0xffu) : (pkB & 0xffu);

        outr[lane] = xr[(int)iA * 3 + c1];
        if (lane < 16)
            outr[32 + lane] = xr[(int)iB * 3 + c2];

        xr   += 192;
        outr += 48;
    }
}

extern "C" void kernel_launch(void* const* d_in, const int* in_sizes, int n_in,
                              void* d_out, int out_size)
{
    const float* x   = (const float*)d_in[0];
    float*       out = (float*)d_out;
    int nrows = in_sizes[0] / 192;
    int rowsPerBlock = WPB * RPW;
    int grid = (nrows + rowsPerBlock - 1) / rowsPerBlock;
    vecnorm_topk_kernel<<<grid, WPB * 32>>>(x, out, nrows);
}